// round 13
// baseline (speedup 1.0000x reference)
#include <cuda_runtime.h>
#include <cuda_bf16.h>
#include <cstdint>

#define N_NODES 30000
#define N_PAD   30080      // 235 * 128
#define N_EDGES 480000
#define DIN     1000
#define KSEC    1024       // padded section K
#define KTOT    3072       // 3 sections
#define NH      8
#define FH      32
#define HF      256        // NH*FH
#define DEMB    64
#define NEG     0.2f
#define NBLK    235        // N_PAD / 128

// ---------------- scratch (device globals; no allocation allowed) ----------
__device__ __nv_bfloat16 g_xhi[(size_t)N_PAD*KSEC];
__device__ __nv_bfloat16 g_xlo[(size_t)N_PAD*KSEC];
__device__ __nv_bfloat16 g_wB [(size_t)HF*KTOT];    // B' [N=256][K=3072] K-major
__device__ float g_h   [(size_t)N_NODES*HF];   // x@W
__device__ float g_as  [N_NODES*NH];
__device__ float g_ad  [N_NODES*NH];
__device__ int   g_deg [N_NODES];
__device__ int   g_off [N_NODES];
__device__ int   g_cur [N_NODES];
__device__ int   g_bsum[NBLK];
__device__ int   g_bpre[NBLK];
__device__ int   g_srcs[N_EDGES];              // src ids sorted by dst
__device__ float g_gat [(size_t)N_NODES*HF];   // relu(GAT out + bias)
// recon operands (bf16x3): A' rows [d_hi | d_lo | d_hi], B' rows [w_hi|w_hi|w_lo]
__device__ __nv_bfloat16 g_dB [(size_t)N_PAD*96];
__device__ __nv_bfloat16 g_w2B[(size_t)1024*96];

// ======================= helpers ============================================
__device__ __forceinline__ uint32_t smem_to_u32(const void* p) {
    uint32_t a;
    asm("{ .reg .u64 t; cvta.to.shared.u64 t, %1; cvt.u32.u64 %0, t; }"
        : "=r"(a) : "l"(p));
    return a;
}
__device__ __forceinline__ void cpasync16(uint32_t saddr, const void* gp) {
    asm volatile("cp.async.cg.shared.global [%0], [%1], 16;" :: "r"(saddr), "l"(gp));
}
__device__ __forceinline__ void ldm_x4(uint32_t& r0, uint32_t& r1,
                                       uint32_t& r2, uint32_t& r3, uint32_t a) {
    asm volatile("ldmatrix.sync.aligned.m8n8.x4.shared.b16 {%0,%1,%2,%3}, [%4];"
                 : "=r"(r0), "=r"(r1), "=r"(r2), "=r"(r3) : "r"(a));
}
__device__ __forceinline__ void mma_bf16(float* c, const uint32_t* a,
                                         uint32_t b0, uint32_t b1) {
    asm volatile(
        "mma.sync.aligned.m16n8k16.row.col.f32.bf16.bf16.f32 "
        "{%0,%1,%2,%3}, {%4,%5,%6,%7}, {%8,%9}, {%0,%1,%2,%3};"
        : "+f"(c[0]), "+f"(c[1]), "+f"(c[2]), "+f"(c[3])
        : "r"(a[0]), "r"(a[1]), "r"(a[2]), "r"(a[3]), "r"(b0), "r"(b1));
}
__device__ __forceinline__ uint32_t pack_bf16x2(float a, float b) {
    __nv_bfloat16 ha = __float2bfloat16(a), hb = __float2bfloat16(b);
    return (uint32_t)__bfloat16_as_ushort(ha) |
           ((uint32_t)__bfloat16_as_ushort(hb) << 16);
}

// ======================= split / pack kernels ===============================
// 8 elems/thread; also zeroes g_deg
__global__ void split_x_kernel(const float* __restrict__ x) {
    size_t g8 = ((size_t)blockIdx.x * blockDim.x + threadIdx.x);
    if (g8 < N_NODES) g_deg[g8] = 0;
    if (g8 >= (size_t)N_PAD * KSEC / 8) return;
    size_t idx = g8 * 8;
    int r  = (int)(idx >> 10);
    int c0 = (int)(idx & 1023);
    float v[8];
    if (r < N_NODES && c0 + 7 < DIN) {
        const float4 f0 = *(const float4*)&x[(size_t)r * DIN + c0];
        const float4 f1 = *(const float4*)&x[(size_t)r * DIN + c0 + 4];
        v[0]=f0.x; v[1]=f0.y; v[2]=f0.z; v[3]=f0.w;
        v[4]=f1.x; v[5]=f1.y; v[6]=f1.z; v[7]=f1.w;
    } else {
        #pragma unroll
        for (int i = 0; i < 8; i++) {
            int c = c0 + i;
            v[i] = (r < N_NODES && c < DIN) ? x[(size_t)r * DIN + c] : 0.f;
        }
    }
    __nv_bfloat16 hi[8], lo[8];
    #pragma unroll
    for (int i = 0; i < 8; i++) {
        hi[i] = __float2bfloat16(v[i]);
        lo[i] = __float2bfloat16(v[i] - __bfloat162float(hi[i]));
    }
    *(uint4*)&g_xhi[idx] = *(const uint4*)hi;
    *(uint4*)&g_xlo[idx] = *(const uint4*)lo;
}
// packs g_wB, g_w2B; also counts in-degrees (g_deg zeroed by split_x before)
__global__ void build_wB_kernel(const float* __restrict__ W,
                                const float* __restrict__ W2,
                                const int* __restrict__ ei) {
    int idx = blockIdx.x * blockDim.x + threadIdx.x;       // over 256*3072
    if (idx < N_EDGES) atomicAdd(&g_deg[ei[N_EDGES + idx]], 1);
    if (idx < 1024 * 96) {
        int n  = idx / 96;
        int kk = idx - n * 96;
        int sec = kk >> 5, k = kk & 31;
        float v = (n < DIN) ? W2[(size_t)k * DIN + n] : 0.f;
        __nv_bfloat16 hi = __float2bfloat16(v);
        g_w2B[idx] = (sec == 2) ? __float2bfloat16(v - __bfloat162float(hi)) : hi;
    }
    if (idx >= HF * KTOT) return;
    int n  = idx / KTOT;
    int kk = idx % KTOT;
    int s  = kk >> 10;
    int k  = kk & 1023;
    float v = (k < DIN) ? W[(size_t)k * HF + n] : 0.f;
    __nv_bfloat16 hi = __float2bfloat16(v);
    g_wB[idx] = (s == 2) ? __float2bfloat16(v - __bfloat162float(hi)) : hi;
}

// ======================= bf16 mma.sync GEMM1 (+fused att) ===================
// BM=64 BN=128 BK=32, 256 threads, 8 warps (2 m x 4 n), warp tile 32x32.
// 3 slots / 2 preloads / single barrier per chunk. 3 CTAs/SM.
#define BKC  32
#define LDSM 40           // BKC + 8 pad elements (80B row stride)
#define NCH  96           // 3072/32
#define ASTG 5120u        // 64*40*2
#define BSTG 10240u       // 128*40*2
#define STGB (ASTG+BSTG)  // 15360 per stage
#define GSMT (3u*STGB)    // 46080

__global__ void __launch_bounds__(256, 3) gemm1_mma_kernel(
    const float* __restrict__ att_src, const float* __restrict__ att_dst)
{
    extern __shared__ char gsm[];
    const uint32_t sb = smem_to_u32(gsm);
    const int t    = threadIdx.x;
    const int lane = t & 31;
    const int wid  = t >> 5;
    const int wm   = (wid & 1) * 32;
    const int wn   = (wid >> 1) * 32;
    const int m0   = blockIdx.y * 64;
    const int n0   = blockIdx.x * 128;

    float acc[2][4][4];
    #pragma unroll
    for (int i = 0; i < 2; i++)
        #pragma unroll
        for (int j = 0; j < 4; j++)
            #pragma unroll
            for (int q = 0; q < 4; q++) acc[i][j][q] = 0.f;

    const int a_r = (lane & 7) + ((lane >> 3) & 1) * 8;
    const int a_c = (lane >> 4) * 8;
    const int b_r = ((lane >> 4) & 1) * 8 + (lane & 7);
    const int b_c = ((lane >> 3) & 1) * 8;

    auto sAaddr = [&](int s, int r, int c) -> uint32_t {
        return sb + (uint32_t)s * STGB + (uint32_t)r * (LDSM * 2) + (uint32_t)c * 2;
    };
    auto sBaddr = [&](int s, int r, int c) -> uint32_t {
        return sb + (uint32_t)s * STGB + ASTG + (uint32_t)r * (LDSM * 2) + (uint32_t)c * 2;
    };

    // stage: A 64x32 (256 x16B chunks, 1/thread), B 128x32 (512 chunks, 2/thread)
    auto load_stage = [&](int s, int c) {
        const int kp  = c * BKC;
        const int sec = kp >> 10;
        const int ko  = kp & 1023;
        const __nv_bfloat16* Abase = ((sec == 1) ? g_xlo : g_xhi)
                                     + (size_t)m0 * KSEC + ko;
        const __nv_bfloat16* Bbase = g_wB + (size_t)n0 * KTOT + kp;
        {
            int r  = t >> 2;
            int ch = (t & 3) * 8;
            cpasync16(sAaddr(s, r, ch), Abase + (size_t)r * KSEC + ch);
        }
        #pragma unroll
        for (int i = 0; i < 2; i++) {
            int u  = t + 256 * i;
            int r  = u >> 2;
            int ch = (u & 3) * 8;
            cpasync16(sBaddr(s, r, ch), Bbase + (size_t)r * KTOT + ch);
        }
    };

    load_stage(0, 0);
    asm volatile("cp.async.commit_group;" ::: "memory");
    load_stage(1, 1);
    asm volatile("cp.async.commit_group;" ::: "memory");

    for (int c = 0; c < NCH; c++) {
        const int s = c % 3;
        asm volatile("cp.async.wait_group 1;" ::: "memory");
        __syncthreads();
        if (c + 2 < NCH) load_stage((c + 2) % 3, c + 2);
        asm volatile("cp.async.commit_group;" ::: "memory");

        #pragma unroll
        for (int ks = 0; ks < 2; ks++) {
            const int kb = ks * 16;
            uint32_t a[2][4];
            #pragma unroll
            for (int mt = 0; mt < 2; mt++)
                ldm_x4(a[mt][0], a[mt][1], a[mt][2], a[mt][3],
                       sAaddr(s, wm + mt * 16 + a_r, kb + a_c));
            #pragma unroll
            for (int nt4 = 0; nt4 < 2; nt4++) {
                uint32_t b0, b1, b2, b3;
                ldm_x4(b0, b1, b2, b3, sBaddr(s, wn + nt4 * 16 + b_r, kb + b_c));
                #pragma unroll
                for (int mt = 0; mt < 2; mt++) {
                    mma_bf16(acc[mt][nt4 * 2 + 0], a[mt], b0, b1);
                    mma_bf16(acc[mt][nt4 * 2 + 1], a[mt], b2, b3);
                }
            }
        }
    }

    // ---- epilogue 1: write C fragments to g_h ----
    #pragma unroll
    for (int mt = 0; mt < 2; mt++) {
        const int r0 = m0 + wm + mt * 16 + (lane >> 2);
        #pragma unroll
        for (int nt = 0; nt < 4; nt++) {
            const int cc = n0 + wn + nt * 8 + (lane & 3) * 2;
            if (r0 < N_NODES)
                *(float2*)&g_h[(size_t)r0 * HF + cc] =
                    make_float2(acc[mt][nt][0], acc[mt][nt][1]);
            if (r0 + 8 < N_NODES)
                *(float2*)&g_h[(size_t)(r0 + 8) * HF + cc] =
                    make_float2(acc[mt][nt][2], acc[mt][nt][3]);
        }
    }

    // ---- epilogue 2: fused a_s / a_d (warp tile = exactly one head) ----
    {
        const int head = (n0 + wn) >> 5;
        float2 sv[4], dv[4];
        #pragma unroll
        for (int nt = 0; nt < 4; nt++) {
            const int cc = n0 + wn + nt * 8 + (lane & 3) * 2;
            sv[nt] = *(const float2*)&att_src[cc];
            dv[nt] = *(const float2*)&att_dst[cc];
        }
        #pragma unroll
        for (int mt = 0; mt < 2; mt++) {
            float vs0 = 0.f, vd0 = 0.f, vs1 = 0.f, vd1 = 0.f;
            #pragma unroll
            for (int nt = 0; nt < 4; nt++) {
                vs0 += acc[mt][nt][0] * sv[nt].x + acc[mt][nt][1] * sv[nt].y;
                vd0 += acc[mt][nt][0] * dv[nt].x + acc[mt][nt][1] * dv[nt].y;
                vs1 += acc[mt][nt][2] * sv[nt].x + acc[mt][nt][3] * sv[nt].y;
                vd1 += acc[mt][nt][2] * dv[nt].x + acc[mt][nt][3] * dv[nt].y;
            }
            vs0 += __shfl_xor_sync(0xffffffffu, vs0, 1);
            vs0 += __shfl_xor_sync(0xffffffffu, vs0, 2);
            vd0 += __shfl_xor_sync(0xffffffffu, vd0, 1);
            vd0 += __shfl_xor_sync(0xffffffffu, vd0, 2);
            vs1 += __shfl_xor_sync(0xffffffffu, vs1, 1);
            vs1 += __shfl_xor_sync(0xffffffffu, vs1, 2);
            vd1 += __shfl_xor_sync(0xffffffffu, vd1, 1);
            vd1 += __shfl_xor_sync(0xffffffffu, vd1, 2);
            if ((lane & 3) == 0) {
                const int r0 = m0 + wm + mt * 16 + (lane >> 2);
                if (r0 < N_NODES)     { g_as[r0*NH + head] = vs0; g_ad[r0*NH + head] = vd0; }
                if (r0 + 8 < N_NODES) { g_as[(r0+8)*NH + head] = vs1; g_ad[(r0+8)*NH + head] = vd1; }
            }
        }
    }
}

// ======================= recon bf16 mma GEMM ================================
#define RLD  104          // 96 + 8 pad
#define RSMT (2u*128u*RLD*2u)   // 53248

__global__ void __launch_bounds__(256) recon_mma_kernel(
    const float* __restrict__ bias, float* __restrict__ recon)
{
    extern __shared__ char rsm[];
    const uint32_t sb = smem_to_u32(rsm);
    const int t    = threadIdx.x;
    const int lane = t & 31;
    const int wid  = t >> 5;
    const int wm   = (wid & 3) * 32;
    const int wn   = (wid >> 2) * 64;
    const int m0   = blockIdx.y * 128;
    const int n0   = blockIdx.x * 128;

    auto sAaddr = [&](int r, int c) -> uint32_t {
        return sb + (uint32_t)r * (RLD * 2) + (uint32_t)c * 2;
    };
    auto sBaddr = [&](int r, int c) -> uint32_t {
        return sb + 128u * RLD * 2u + (uint32_t)r * (RLD * 2) + (uint32_t)c * 2;
    };

    #pragma unroll
    for (int i = 0; i < 6; i++) {
        int u  = t + 256 * i;
        int r  = u / 12;
        int ch = (u % 12) * 8;
        cpasync16(sAaddr(r, ch), g_dB  + (size_t)(m0 + r) * 96 + ch);
        cpasync16(sBaddr(r, ch), g_w2B + (size_t)(n0 + r) * 96 + ch);
    }
    asm volatile("cp.async.commit_group;" ::: "memory");

    float acc[2][8][4];
    #pragma unroll
    for (int i = 0; i < 2; i++)
        #pragma unroll
        for (int j = 0; j < 8; j++)
            #pragma unroll
            for (int q = 0; q < 4; q++) acc[i][j][q] = 0.f;

    const int a_r = (lane & 7) + ((lane >> 3) & 1) * 8;
    const int a_c = (lane >> 4) * 8;
    const int b_r = ((lane >> 4) & 1) * 8 + (lane & 7);
    const int b_c = ((lane >> 3) & 1) * 8;

    asm volatile("cp.async.wait_group 0;" ::: "memory");
    __syncthreads();

    #pragma unroll
    for (int ks = 0; ks < 6; ks++) {
        const int kb = ks * 16;
        uint32_t a[2][4];
        #pragma unroll
        for (int mt = 0; mt < 2; mt++)
            ldm_x4(a[mt][0], a[mt][1], a[mt][2], a[mt][3],
                   sAaddr(wm + mt * 16 + a_r, kb + a_c));
        #pragma unroll
        for (int nt4 = 0; nt4 < 4; nt4++) {
            uint32_t b0, b1, b2, b3;
            ldm_x4(b0, b1, b2, b3, sBaddr(wn + nt4 * 16 + b_r, kb + b_c));
            #pragma unroll
            for (int mt = 0; mt < 2; mt++) {
                mma_bf16(acc[mt][nt4 * 2 + 0], a[mt], b0, b1);
                mma_bf16(acc[mt][nt4 * 2 + 1], a[mt], b2, b3);
            }
        }
    }

    #pragma unroll
    for (int mt = 0; mt < 2; mt++) {
        const int r0 = m0 + wm + mt * 16 + (lane >> 2);
        #pragma unroll
        for (int nt = 0; nt < 8; nt++) {
            const int cc = n0 + wn + nt * 8 + (lane & 3) * 2;
            if (cc >= DIN) continue;
            const float2 bv = *(const float2*)&bias[cc];
            if (r0 < N_NODES)
                *(float2*)&recon[(size_t)r0 * DIN + cc] =
                    make_float2(acc[mt][nt][0] + bv.x, acc[mt][nt][1] + bv.y);
            if (r0 + 8 < N_NODES)
                *(float2*)&recon[(size_t)(r0 + 8) * DIN + cc] =
                    make_float2(acc[mt][nt][2] + bv.x, acc[mt][nt][3] + bv.y);
        }
    }
}

// ---------------- fused z + d kernel (d emitted as bf16x3 A-matrix) ---------
__global__ void __launch_bounds__(256) zd_kernel(
    const float* __restrict__ emb_W, const float* __restrict__ emb_b,
    const float* __restrict__ dec_W1, const float* __restrict__ dec_b1,
    float* __restrict__ z)
{
    __shared__ float sbuf[10432];
    float (*As)[132] = (float(*)[132])sbuf;
    float (*Bs)[68]  = (float(*)[68])(sbuf + 4224);
    float (*zs)[65]  = (float(*)[65])sbuf;
    float (*W1s)[33] = (float(*)[33])(sbuf + 8320);

    const int t  = threadIdx.x;
    const int tx = t & 15, ty = t >> 4;
    const int m0 = blockIdx.x * 128;

    float acc[8][4];
    #pragma unroll
    for (int i=0;i<8;i++)
        #pragma unroll
        for (int j=0;j<4;j++) acc[i][j]=0.f;

    for (int k0=0;k0<HF;k0+=32) {
        #pragma unroll
        for (int i=0;i<16;i++){
            int lin = t + 256*i;
            int r = lin >> 5, c = lin & 31;
            As[c][r] = (m0+r < N_NODES) ? g_gat[(size_t)(m0+r)*HF + k0+c] : 0.f;
        }
        #pragma unroll
        for (int i=0;i<8;i++){
            int lin = t + 256*i;
            int r = lin >> 6, c = lin & 63;
            Bs[r][c] = emb_W[(size_t)(k0+r)*DEMB + c];
        }
        __syncthreads();
        #pragma unroll
        for (int k=0;k<32;k++){
            float ra[8], rb[4];
            #pragma unroll
            for (int i=0;i<8;i++) ra[i]=As[k][ty*8+i];
            #pragma unroll
            for (int j=0;j<4;j++) rb[j]=Bs[k][tx*4+j];
            #pragma unroll
            for (int i=0;i<8;i++)
                #pragma unroll
                for (int j=0;j<4;j++) acc[i][j] += ra[i]*rb[j];
        }
        __syncthreads();
    }

    const float4 bz = *(const float4*)&emb_b[tx*4];
    #pragma unroll
    for (int i=0;i<8;i++){
        int m = m0 + ty*8 + i;
        float4 v = make_float4(acc[i][0]+bz.x, acc[i][1]+bz.y,
                               acc[i][2]+bz.z, acc[i][3]+bz.w);
        zs[ty*8+i][tx*4+0]=v.x; zs[ty*8+i][tx*4+1]=v.y;
        zs[ty*8+i][tx*4+2]=v.z; zs[ty*8+i][tx*4+3]=v.w;
        if (m < N_NODES) *(float4*)&z[(size_t)m*DEMB + tx*4] = v;
    }
    #pragma unroll
    for (int i=0;i<8;i++){
        int lin = t + 256*i;
        int r = lin >> 5, c = lin & 31;
        W1s[r][c] = dec_W1[(size_t)r*FH + c];
    }
    __syncthreads();

    float acc2[8][2];
    #pragma unroll
    for (int i=0;i<8;i++){ acc2[i][0]=0.f; acc2[i][1]=0.f; }
    #pragma unroll 8
    for (int k=0;k<DEMB;k++){
        float rb0 = W1s[k][tx*2], rb1 = W1s[k][tx*2+1];
        #pragma unroll
        for (int i=0;i<8;i++){
            float ra = zs[ty*8+i][k];
            acc2[i][0] += ra*rb0;
            acc2[i][1] += ra*rb1;
        }
    }
    const float b0 = dec_b1[tx*2], b1 = dec_b1[tx*2+1];
    const int k2 = tx*2;
    #pragma unroll
    for (int i=0;i<8;i++){
        int m = m0 + ty*8 + i;
        if (m < N_NODES){
            float v0 = fmaxf(acc2[i][0]+b0, 0.f);
            float v1 = fmaxf(acc2[i][1]+b1, 0.f);
            __nv_bfloat16 h0 = __float2bfloat16(v0);
            __nv_bfloat16 h1 = __float2bfloat16(v1);
            uint32_t hi2 = (uint32_t)__bfloat16_as_ushort(h0) |
                           ((uint32_t)__bfloat16_as_ushort(h1) << 16);
            uint32_t lo2 = pack_bf16x2(v0 - __bfloat162float(h0),
                                       v1 - __bfloat162float(h1));
            size_t base = (size_t)m * 96;
            *(uint32_t*)&g_dB[base + k2]      = hi2;
            *(uint32_t*)&g_dB[base + 32 + k2] = lo2;
            *(uint32_t*)&g_dB[base + 64 + k2] = hi2;
        }
    }
}

// ---------------- CSR build: deterministic two-level scan --------------------
__global__ void __launch_bounds__(128) bsum_kernel(){
    const int t = threadIdx.x;
    const int node = blockIdx.x * 128 + t;
    int deg = (node < N_NODES) ? g_deg[node] : 0;
    #pragma unroll
    for (int s = 16; s > 0; s >>= 1) deg += __shfl_down_sync(0xffffffffu, deg, s);
    __shared__ int ws[4];
    if ((t & 31) == 0) ws[t >> 5] = deg;
    __syncthreads();
    if (t == 0) g_bsum[blockIdx.x] = ws[0] + ws[1] + ws[2] + ws[3];
}
__global__ void __launch_bounds__(256) bscan_kernel(){
    __shared__ int sm[256];
    const int t = threadIdx.x;
    int v = (t < NBLK) ? g_bsum[t] : 0;
    sm[t] = v; __syncthreads();
    for (int s = 1; s < 256; s <<= 1) {
        int u = (t >= s) ? sm[t - s] : 0;
        __syncthreads();
        sm[t] += u;
        __syncthreads();
    }
    if (t < NBLK) g_bpre[t] = sm[t] - v;   // exclusive prefix
}
__global__ void __launch_bounds__(128) offset_kernel(){
    const int t    = threadIdx.x;
    const int lane = t & 31;
    const int w    = t >> 5;
    const int node = blockIdx.x * 128 + t;
    const int deg  = (node < N_NODES) ? g_deg[node] : 0;

    int incl = deg;
    #pragma unroll
    for (int s = 1; s < 32; s <<= 1) {
        int v = __shfl_up_sync(0xffffffffu, incl, s);
        if (lane >= s) incl += v;
    }
    __shared__ int wsum[4];
    if (lane == 31) wsum[w] = incl;
    __syncthreads();
    if (t == 0) {
        int a = wsum[0], b = wsum[1], c = wsum[2];
        wsum[3] = a + b + c; wsum[2] = a + b; wsum[1] = a; wsum[0] = 0;
    }
    __syncthreads();
    const int off = g_bpre[blockIdx.x] + wsum[w] + incl - deg;
    if (node < N_NODES) { g_off[node] = off; g_cur[node] = off; }
}
__global__ void scatter_kernel(const int* __restrict__ ei){
    int e = blockIdx.x*blockDim.x+threadIdx.x;
    if (e<N_EDGES){
        int d = ei[N_EDGES+e];
        int p = atomicAdd(&g_cur[d],1);
        g_srcs[p] = ei[e];
    }
}

// ---------------- softmax + aggregate: warp per node ------------------------
__global__ void __launch_bounds__(256) agg_kernel(const float* __restrict__ bias_gat)
{
    const int wid  = threadIdx.x >> 5;
    const int lane = threadIdx.x & 31;
    const int node = blockIdx.x * 8 + wid;
    if (node >= N_NODES) return;

    const int off = g_off[node];
    const int deg = g_deg[node];

    float adv = 0.f, den = 0.f, pv = 0.f;
    if (lane < NH) {
        adv = g_ad[node * NH + lane];
        float l = g_as[node * NH + lane] + adv;
        l = (l > 0.f) ? l : NEG * l;
        pv = expf(l);
        den = pv;
    }

    const float* hrow = g_h + (size_t)node * HF;
    float acc[NH];
    #pragma unroll
    for (int h = 0; h < NH; h++)
        acc[h] = hrow[h * FH + lane] * __shfl_sync(0xffffffffu, pv, h);

    for (int e = 0; e < deg; e++) {
        const int s = g_srcs[off + e];
        float pe = 0.f;
        if (lane < NH) {
            float l = g_as[s * NH + lane] + adv;
            l = (l > 0.f) ? l : NEG * l;
            pe = expf(l);
            den += pe;
        }
        const float* srow = g_h + (size_t)s * HF;
        #pragma unroll
        for (int h = 0; h < NH; h++)
            acc[h] += srow[h * FH + lane] * __shfl_sync(0xffffffffu, pe, h);
    }

    #pragma unroll
    for (int h = 0; h < NH; h++) {
        const float d = __shfl_sync(0xffffffffu, den, h);
        const float v = acc[h] / d + bias_gat[h * FH + lane];
        g_gat[(size_t)node * HF + h * FH + lane] = fmaxf(v, 0.f);
    }
}

// ---------------- launch -----------------------------------------------------
extern "C" void kernel_launch(void* const* d_in, const int* in_sizes, int n_in,
                              void* d_out, int out_size)
{
    const float* x        = (const float*)d_in[0];
    const int*   ei       = (const int*)  d_in[1];
    const float* W        = (const float*)d_in[3];
    const float* att_src  = (const float*)d_in[4];
    const float* att_dst  = (const float*)d_in[5];
    const float* bias_gat = (const float*)d_in[6];
    const float* emb_W    = (const float*)d_in[7];
    const float* emb_b    = (const float*)d_in[8];
    const float* dec_W1   = (const float*)d_in[9];
    const float* dec_b1   = (const float*)d_in[10];
    const float* dec_W2   = (const float*)d_in[11];
    const float* dec_b2   = (const float*)d_in[12];

    float* recon = (float*)d_out;                              // [N, DIN]
    float* z     = (float*)d_out + (size_t)N_NODES*DIN;        // [N, DEMB]

    cudaFuncSetAttribute(gemm1_mma_kernel,
                         cudaFuncAttributeMaxDynamicSharedMemorySize, GSMT);
    cudaFuncSetAttribute(recon_mma_kernel,
                         cudaFuncAttributeMaxDynamicSharedMemorySize, RSMT);

    const int MB = (N_NODES + 127)/128;   // 235
    const int MB64 = N_PAD/64;            // 470

    // 0) operand prep (split zeroes g_deg; build_wB counts + packs W,W2)
    split_x_kernel<<<(int)(((size_t)N_PAD*KSEC/8 + 255)/256), 256>>>(x);
    build_wB_kernel<<<(HF*KTOT + 255)/256, 256>>>(W, dec_W2, ei);
    // 1) h = x @ W via mma.sync bf16x3 (+ fused a_s/a_d); BM=64, 3 CTAs/SM
    gemm1_mma_kernel<<<dim3(2, MB64), 256, GSMT>>>(att_src, att_dst);
    // 2) CSR finish: deterministic two-level scan + scatter
    bsum_kernel   <<<MB, 128>>>();
    bscan_kernel  <<<1, 256>>>();
    offset_kernel <<<MB, 128>>>();
    scatter_kernel<<<(N_EDGES+255)/256,256>>>(ei);
    // 3) attention softmax + aggregate + bias + relu (warp per node)
    agg_kernel<<<(N_NODES+7)/8, 256>>>(bias_gat);
    // 4+5) fused z and d (d emitted as bf16x3)
    zd_kernel<<<MB, 256>>>(emb_W, emb_b, dec_W1, dec_b1, z);
    // 6) recon = d @ dec_W2 + dec_b2 via mma.sync bf16x3
    recon_mma_kernel<<<dim3(8, MB), 256, RSMT>>>(dec_b2, recon);
}

// round 14
// speedup vs baseline: 1.1486x; 1.1486x over previous
#include <cuda_runtime.h>
#include <cuda_bf16.h>
#include <cstdint>

#define N_NODES 30000
#define N_PAD   30080      // 235 * 128
#define N_EDGES 480000
#define DIN     1000
#define KSEC    1024       // padded section K
#define KTOT    3072       // 3 sections
#define NH      8
#define FH      32
#define HF      256        // NH*FH
#define DEMB    64
#define NEG     0.2f
#define NBLK    235        // N_PAD / 128

// ---------------- scratch (device globals; no allocation allowed) ----------
__device__ __nv_bfloat16 g_xhi[(size_t)N_PAD*KSEC];
__device__ __nv_bfloat16 g_xlo[(size_t)N_PAD*KSEC];
__device__ __nv_bfloat16 g_wB [(size_t)HF*KTOT];    // B' [N=256][K=3072] K-major
__device__ float g_h   [(size_t)N_NODES*HF];   // x@W
__device__ float g_as  [N_NODES*NH];
__device__ float g_ad  [N_NODES*NH];
__device__ int   g_deg [N_NODES];
__device__ int   g_off [N_NODES];
__device__ int   g_cur [N_NODES];
__device__ int   g_bsum[NBLK];
__device__ int   g_bpre[NBLK];
__device__ int   g_srcs[N_EDGES];              // src ids sorted by dst
__device__ float g_gat [(size_t)N_NODES*HF];   // relu(GAT out + bias)
// recon operands (bf16x3): A' rows [d_hi | d_lo | d_hi], B' rows [w_hi|w_hi|w_lo]
__device__ __nv_bfloat16 g_dB [(size_t)N_PAD*96];
__device__ __nv_bfloat16 g_w2B[(size_t)1024*96];

// ======================= helpers ============================================
__device__ __forceinline__ uint32_t smem_to_u32(const void* p) {
    uint32_t a;
    asm("{ .reg .u64 t; cvta.to.shared.u64 t, %1; cvt.u32.u64 %0, t; }"
        : "=r"(a) : "l"(p));
    return a;
}
__device__ __forceinline__ void cpasync16(uint32_t saddr, const void* gp) {
    asm volatile("cp.async.cg.shared.global [%0], [%1], 16;" :: "r"(saddr), "l"(gp));
}
__device__ __forceinline__ void ldm_x4(uint32_t& r0, uint32_t& r1,
                                       uint32_t& r2, uint32_t& r3, uint32_t a) {
    asm volatile("ldmatrix.sync.aligned.m8n8.x4.shared.b16 {%0,%1,%2,%3}, [%4];"
                 : "=r"(r0), "=r"(r1), "=r"(r2), "=r"(r3) : "r"(a));
}
__device__ __forceinline__ void mma_bf16(float* c, const uint32_t* a,
                                         uint32_t b0, uint32_t b1) {
    asm volatile(
        "mma.sync.aligned.m16n8k16.row.col.f32.bf16.bf16.f32 "
        "{%0,%1,%2,%3}, {%4,%5,%6,%7}, {%8,%9}, {%0,%1,%2,%3};"
        : "+f"(c[0]), "+f"(c[1]), "+f"(c[2]), "+f"(c[3])
        : "r"(a[0]), "r"(a[1]), "r"(a[2]), "r"(a[3]), "r"(b0), "r"(b1));
}
__device__ __forceinline__ uint32_t pack_bf16x2(float a, float b) {
    __nv_bfloat16 ha = __float2bfloat16(a), hb = __float2bfloat16(b);
    return (uint32_t)__bfloat16_as_ushort(ha) |
           ((uint32_t)__bfloat16_as_ushort(hb) << 16);
}
__device__ __forceinline__ uint32_t swz(uint32_t off) {   // 128B XOR swizzle
    return off ^ ((off >> 3) & 0x70);
}

// ======================= split / pack kernels ===============================
// 8 elems/thread; also zeroes g_deg
__global__ void split_x_kernel(const float* __restrict__ x) {
    size_t g8 = ((size_t)blockIdx.x * blockDim.x + threadIdx.x);
    if (g8 < N_NODES) g_deg[g8] = 0;
    if (g8 >= (size_t)N_PAD * KSEC / 8) return;
    size_t idx = g8 * 8;
    int r  = (int)(idx >> 10);
    int c0 = (int)(idx & 1023);
    float v[8];
    if (r < N_NODES && c0 + 7 < DIN) {
        const float4 f0 = *(const float4*)&x[(size_t)r * DIN + c0];
        const float4 f1 = *(const float4*)&x[(size_t)r * DIN + c0 + 4];
        v[0]=f0.x; v[1]=f0.y; v[2]=f0.z; v[3]=f0.w;
        v[4]=f1.x; v[5]=f1.y; v[6]=f1.z; v[7]=f1.w;
    } else {
        #pragma unroll
        for (int i = 0; i < 8; i++) {
            int c = c0 + i;
            v[i] = (r < N_NODES && c < DIN) ? x[(size_t)r * DIN + c] : 0.f;
        }
    }
    __nv_bfloat16 hi[8], lo[8];
    #pragma unroll
    for (int i = 0; i < 8; i++) {
        hi[i] = __float2bfloat16(v[i]);
        lo[i] = __float2bfloat16(v[i] - __bfloat162float(hi[i]));
    }
    *(uint4*)&g_xhi[idx] = *(const uint4*)hi;
    *(uint4*)&g_xlo[idx] = *(const uint4*)lo;
}
// packs g_wB, g_w2B; also counts in-degrees (g_deg zeroed by split_x before)
__global__ void build_wB_kernel(const float* __restrict__ W,
                                const float* __restrict__ W2,
                                const int* __restrict__ ei) {
    int idx = blockIdx.x * blockDim.x + threadIdx.x;       // over 256*3072
    if (idx < N_EDGES) atomicAdd(&g_deg[ei[N_EDGES + idx]], 1);
    if (idx < 1024 * 96) {
        int n  = idx / 96;
        int kk = idx - n * 96;
        int sec = kk >> 5, k = kk & 31;
        float v = (n < DIN) ? W2[(size_t)k * DIN + n] : 0.f;
        __nv_bfloat16 hi = __float2bfloat16(v);
        g_w2B[idx] = (sec == 2) ? __float2bfloat16(v - __bfloat162float(hi)) : hi;
    }
    if (idx >= HF * KTOT) return;
    int n  = idx / KTOT;
    int kk = idx % KTOT;
    int s  = kk >> 10;
    int k  = kk & 1023;
    float v = (k < DIN) ? W[(size_t)k * HF + n] : 0.f;
    __nv_bfloat16 hi = __float2bfloat16(v);
    g_wB[idx] = (s == 2) ? __float2bfloat16(v - __bfloat162float(hi)) : hi;
}

// ======================= bf16 mma.sync GEMM1 (+fused att) ===================
// BM=64 BN=128 BK=64, 256 threads, 8 warps (2 m x 4 n), warp tile 32x32.
// XOR-128B swizzled smem (no pad), 3 slots / 2 preloads, 3 CTAs/SM.
#define BKC  64
#define NCH  48           // 3072/64
#define ASTG 8192u        // 64 rows * 128 B
#define BSTG 16384u       // 128 rows * 128 B
#define STGB (ASTG+BSTG)  // 24576 per stage
#define GSMT (3u*STGB)    // 73728

__global__ void __launch_bounds__(256, 3) gemm1_mma_kernel(
    const float* __restrict__ att_src, const float* __restrict__ att_dst)
{
    extern __shared__ char gsm[];
    const uint32_t sb = smem_to_u32(gsm);
    const int t    = threadIdx.x;
    const int lane = t & 31;
    const int wid  = t >> 5;
    const int wm   = (wid & 1) * 32;
    const int wn   = (wid >> 1) * 32;
    const int m0   = blockIdx.y * 64;
    const int n0   = blockIdx.x * 128;

    float acc[2][4][4];
    #pragma unroll
    for (int i = 0; i < 2; i++)
        #pragma unroll
        for (int j = 0; j < 4; j++)
            #pragma unroll
            for (int q = 0; q < 4; q++) acc[i][j][q] = 0.f;

    // fragment row/col (elements)
    const int a_r = (lane & 7) + ((lane >> 3) & 1) * 8;
    const int a_cb = ((lane >> 4) * 8) * 2;          // byte offset in row
    const int b_r = ((lane >> 4) & 1) * 8 + (lane & 7);
    const int b_cb = (((lane >> 3) & 1) * 8) * 2;

    auto sAaddr = [&](int s, int r, int cb) -> uint32_t {
        return sb + (uint32_t)s * STGB + swz((uint32_t)r * 128u + (uint32_t)cb);
    };
    auto sBaddr = [&](int s, int r, int cb) -> uint32_t {
        return sb + (uint32_t)s * STGB + ASTG + swz((uint32_t)r * 128u + (uint32_t)cb);
    };

    // stage: A 64x64 bf16 (512 x16B chunks, 2/thr), B 128x64 (1024 chunks, 4/thr)
    auto load_stage = [&](int s, int c) {
        const int kp  = c * BKC;
        const int sec = kp >> 10;
        const int ko  = kp & 1023;
        const __nv_bfloat16* Abase = ((sec == 1) ? g_xlo : g_xhi)
                                     + (size_t)m0 * KSEC + ko;
        const __nv_bfloat16* Bbase = g_wB + (size_t)n0 * KTOT + kp;
        #pragma unroll
        for (int i = 0; i < 2; i++) {
            int u  = t + 256 * i;
            int r  = u >> 3;            // 0..63
            int cb = (u & 7) * 16;      // byte offset
            cpasync16(sAaddr(s, r, cb), Abase + (size_t)r * KSEC + (cb >> 1));
        }
        #pragma unroll
        for (int i = 0; i < 4; i++) {
            int u  = t + 256 * i;
            int r  = u >> 3;            // 0..127
            int cb = (u & 7) * 16;
            cpasync16(sBaddr(s, r, cb), Bbase + (size_t)r * KTOT + (cb >> 1));
        }
    };

    load_stage(0, 0);
    asm volatile("cp.async.commit_group;" ::: "memory");
    load_stage(1, 1);
    asm volatile("cp.async.commit_group;" ::: "memory");

    for (int c = 0; c < NCH; c++) {
        const int s = c % 3;
        asm volatile("cp.async.wait_group 1;" ::: "memory");
        __syncthreads();
        if (c + 2 < NCH) load_stage((c + 2) % 3, c + 2);
        asm volatile("cp.async.commit_group;" ::: "memory");

        #pragma unroll
        for (int ks = 0; ks < 4; ks++) {
            const int kbb = ks * 32;     // 16 elements = 32 bytes
            uint32_t a[2][4];
            #pragma unroll
            for (int mt = 0; mt < 2; mt++)
                ldm_x4(a[mt][0], a[mt][1], a[mt][2], a[mt][3],
                       sAaddr(s, wm + mt * 16 + a_r, kbb + a_cb));
            #pragma unroll
            for (int nt4 = 0; nt4 < 2; nt4++) {
                uint32_t b0, b1, b2, b3;
                ldm_x4(b0, b1, b2, b3, sBaddr(s, wn + nt4 * 16 + b_r, kbb + b_cb));
                #pragma unroll
                for (int mt = 0; mt < 2; mt++) {
                    mma_bf16(acc[mt][nt4 * 2 + 0], a[mt], b0, b1);
                    mma_bf16(acc[mt][nt4 * 2 + 1], a[mt], b2, b3);
                }
            }
        }
    }

    // ---- epilogue 1: write C fragments to g_h ----
    #pragma unroll
    for (int mt = 0; mt < 2; mt++) {
        const int r0 = m0 + wm + mt * 16 + (lane >> 2);
        #pragma unroll
        for (int nt = 0; nt < 4; nt++) {
            const int cc = n0 + wn + nt * 8 + (lane & 3) * 2;
            if (r0 < N_NODES)
                *(float2*)&g_h[(size_t)r0 * HF + cc] =
                    make_float2(acc[mt][nt][0], acc[mt][nt][1]);
            if (r0 + 8 < N_NODES)
                *(float2*)&g_h[(size_t)(r0 + 8) * HF + cc] =
                    make_float2(acc[mt][nt][2], acc[mt][nt][3]);
        }
    }

    // ---- epilogue 2: fused a_s / a_d (warp tile = exactly one head) ----
    {
        const int head = (n0 + wn) >> 5;
        float2 sv[4], dv[4];
        #pragma unroll
        for (int nt = 0; nt < 4; nt++) {
            const int cc = n0 + wn + nt * 8 + (lane & 3) * 2;
            sv[nt] = *(const float2*)&att_src[cc];
            dv[nt] = *(const float2*)&att_dst[cc];
        }
        #pragma unroll
        for (int mt = 0; mt < 2; mt++) {
            float vs0 = 0.f, vd0 = 0.f, vs1 = 0.f, vd1 = 0.f;
            #pragma unroll
            for (int nt = 0; nt < 4; nt++) {
                vs0 += acc[mt][nt][0] * sv[nt].x + acc[mt][nt][1] * sv[nt].y;
                vd0 += acc[mt][nt][0] * dv[nt].x + acc[mt][nt][1] * dv[nt].y;
                vs1 += acc[mt][nt][2] * sv[nt].x + acc[mt][nt][3] * sv[nt].y;
                vd1 += acc[mt][nt][2] * dv[nt].x + acc[mt][nt][3] * dv[nt].y;
            }
            vs0 += __shfl_xor_sync(0xffffffffu, vs0, 1);
            vs0 += __shfl_xor_sync(0xffffffffu, vs0, 2);
            vd0 += __shfl_xor_sync(0xffffffffu, vd0, 1);
            vd0 += __shfl_xor_sync(0xffffffffu, vd0, 2);
            vs1 += __shfl_xor_sync(0xffffffffu, vs1, 1);
            vs1 += __shfl_xor_sync(0xffffffffu, vs1, 2);
            vd1 += __shfl_xor_sync(0xffffffffu, vd1, 1);
            vd1 += __shfl_xor_sync(0xffffffffu, vd1, 2);
            if ((lane & 3) == 0) {
                const int r0 = m0 + wm + mt * 16 + (lane >> 2);
                if (r0 < N_NODES)     { g_as[r0*NH + head] = vs0; g_ad[r0*NH + head] = vd0; }
                if (r0 + 8 < N_NODES) { g_as[(r0+8)*NH + head] = vs1; g_ad[(r0+8)*NH + head] = vd1; }
            }
        }
    }
}

// ======================= recon bf16 mma GEMM ================================
#define RLD  104          // 96 + 8 pad
#define RSMT (2u*128u*RLD*2u)   // 53248

__global__ void __launch_bounds__(256) recon_mma_kernel(
    const float* __restrict__ bias, float* __restrict__ recon)
{
    extern __shared__ char rsm[];
    const uint32_t sb = smem_to_u32(rsm);
    const int t    = threadIdx.x;
    const int lane = t & 31;
    const int wid  = t >> 5;
    const int wm   = (wid & 3) * 32;
    const int wn   = (wid >> 2) * 64;
    const int m0   = blockIdx.y * 128;
    const int n0   = blockIdx.x * 128;

    auto sAaddr = [&](int r, int c) -> uint32_t {
        return sb + (uint32_t)r * (RLD * 2) + (uint32_t)c * 2;
    };
    auto sBaddr = [&](int r, int c) -> uint32_t {
        return sb + 128u * RLD * 2u + (uint32_t)r * (RLD * 2) + (uint32_t)c * 2;
    };

    #pragma unroll
    for (int i = 0; i < 6; i++) {
        int u  = t + 256 * i;
        int r  = u / 12;
        int ch = (u % 12) * 8;
        cpasync16(sAaddr(r, ch), g_dB  + (size_t)(m0 + r) * 96 + ch);
        cpasync16(sBaddr(r, ch), g_w2B + (size_t)(n0 + r) * 96 + ch);
    }
    asm volatile("cp.async.commit_group;" ::: "memory");

    float acc[2][8][4];
    #pragma unroll
    for (int i = 0; i < 2; i++)
        #pragma unroll
        for (int j = 0; j < 8; j++)
            #pragma unroll
            for (int q = 0; q < 4; q++) acc[i][j][q] = 0.f;

    const int a_r = (lane & 7) + ((lane >> 3) & 1) * 8;
    const int a_c = (lane >> 4) * 8;
    const int b_r = ((lane >> 4) & 1) * 8 + (lane & 7);
    const int b_c = ((lane >> 3) & 1) * 8;

    asm volatile("cp.async.wait_group 0;" ::: "memory");
    __syncthreads();

    #pragma unroll
    for (int ks = 0; ks < 6; ks++) {
        const int kb = ks * 16;
        uint32_t a[2][4];
        #pragma unroll
        for (int mt = 0; mt < 2; mt++)
            ldm_x4(a[mt][0], a[mt][1], a[mt][2], a[mt][3],
                   sAaddr(wm + mt * 16 + a_r, kb + a_c));
        #pragma unroll
        for (int nt4 = 0; nt4 < 4; nt4++) {
            uint32_t b0, b1, b2, b3;
            ldm_x4(b0, b1, b2, b3, sBaddr(wn + nt4 * 16 + b_r, kb + b_c));
            #pragma unroll
            for (int mt = 0; mt < 2; mt++) {
                mma_bf16(acc[mt][nt4 * 2 + 0], a[mt], b0, b1);
                mma_bf16(acc[mt][nt4 * 2 + 1], a[mt], b2, b3);
            }
        }
    }

    #pragma unroll
    for (int mt = 0; mt < 2; mt++) {
        const int r0 = m0 + wm + mt * 16 + (lane >> 2);
        #pragma unroll
        for (int nt = 0; nt < 8; nt++) {
            const int cc = n0 + wn + nt * 8 + (lane & 3) * 2;
            if (cc >= DIN) continue;
            const float2 bv = *(const float2*)&bias[cc];
            if (r0 < N_NODES)
                *(float2*)&recon[(size_t)r0 * DIN + cc] =
                    make_float2(acc[mt][nt][0] + bv.x, acc[mt][nt][1] + bv.y);
            if (r0 + 8 < N_NODES)
                *(float2*)&recon[(size_t)(r0 + 8) * DIN + cc] =
                    make_float2(acc[mt][nt][2] + bv.x, acc[mt][nt][3] + bv.y);
        }
    }
}

// ---------------- fused z + d kernel (d emitted as bf16x3 A-matrix) ---------
__global__ void __launch_bounds__(256) zd_kernel(
    const float* __restrict__ emb_W, const float* __restrict__ emb_b,
    const float* __restrict__ dec_W1, const float* __restrict__ dec_b1,
    float* __restrict__ z)
{
    __shared__ float sbuf[10432];
    float (*As)[132] = (float(*)[132])sbuf;
    float (*Bs)[68]  = (float(*)[68])(sbuf + 4224);
    float (*zs)[65]  = (float(*)[65])sbuf;
    float (*W1s)[33] = (float(*)[33])(sbuf + 8320);

    const int t  = threadIdx.x;
    const int tx = t & 15, ty = t >> 4;
    const int m0 = blockIdx.x * 128;

    float acc[8][4];
    #pragma unroll
    for (int i=0;i<8;i++)
        #pragma unroll
        for (int j=0;j<4;j++) acc[i][j]=0.f;

    for (int k0=0;k0<HF;k0+=32) {
        #pragma unroll
        for (int i=0;i<16;i++){
            int lin = t + 256*i;
            int r = lin >> 5, c = lin & 31;
            As[c][r] = (m0+r < N_NODES) ? g_gat[(size_t)(m0+r)*HF + k0+c] : 0.f;
        }
        #pragma unroll
        for (int i=0;i<8;i++){
            int lin = t + 256*i;
            int r = lin >> 6, c = lin & 63;
            Bs[r][c] = emb_W[(size_t)(k0+r)*DEMB + c];
        }
        __syncthreads();
        #pragma unroll
        for (int k=0;k<32;k++){
            float ra[8], rb[4];
            #pragma unroll
            for (int i=0;i<8;i++) ra[i]=As[k][ty*8+i];
            #pragma unroll
            for (int j=0;j<4;j++) rb[j]=Bs[k][tx*4+j];
            #pragma unroll
            for (int i=0;i<8;i++)
                #pragma unroll
                for (int j=0;j<4;j++) acc[i][j] += ra[i]*rb[j];
        }
        __syncthreads();
    }

    const float4 bz = *(const float4*)&emb_b[tx*4];
    #pragma unroll
    for (int i=0;i<8;i++){
        int m = m0 + ty*8 + i;
        float4 v = make_float4(acc[i][0]+bz.x, acc[i][1]+bz.y,
                               acc[i][2]+bz.z, acc[i][3]+bz.w);
        zs[ty*8+i][tx*4+0]=v.x; zs[ty*8+i][tx*4+1]=v.y;
        zs[ty*8+i][tx*4+2]=v.z; zs[ty*8+i][tx*4+3]=v.w;
        if (m < N_NODES) *(float4*)&z[(size_t)m*DEMB + tx*4] = v;
    }
    #pragma unroll
    for (int i=0;i<8;i++){
        int lin = t + 256*i;
        int r = lin >> 5, c = lin & 31;
        W1s[r][c] = dec_W1[(size_t)r*FH + c];
    }
    __syncthreads();

    float acc2[8][2];
    #pragma unroll
    for (int i=0;i<8;i++){ acc2[i][0]=0.f; acc2[i][1]=0.f; }
    #pragma unroll 8
    for (int k=0;k<DEMB;k++){
        float rb0 = W1s[k][tx*2], rb1 = W1s[k][tx*2+1];
        #pragma unroll
        for (int i=0;i<8;i++){
            float ra = zs[ty*8+i][k];
            acc2[i][0] += ra*rb0;
            acc2[i][1] += ra*rb1;
        }
    }
    const float b0 = dec_b1[tx*2], b1 = dec_b1[tx*2+1];
    const int k2 = tx*2;
    #pragma unroll
    for (int i=0;i<8;i++){
        int m = m0 + ty*8 + i;
        if (m < N_NODES){
            float v0 = fmaxf(acc2[i][0]+b0, 0.f);
            float v1 = fmaxf(acc2[i][1]+b1, 0.f);
            __nv_bfloat16 h0 = __float2bfloat16(v0);
            __nv_bfloat16 h1 = __float2bfloat16(v1);
            uint32_t hi2 = (uint32_t)__bfloat16_as_ushort(h0) |
                           ((uint32_t)__bfloat16_as_ushort(h1) << 16);
            uint32_t lo2 = pack_bf16x2(v0 - __bfloat162float(h0),
                                       v1 - __bfloat162float(h1));
            size_t base = (size_t)m * 96;
            *(uint32_t*)&g_dB[base + k2]      = hi2;
            *(uint32_t*)&g_dB[base + 32 + k2] = lo2;
            *(uint32_t*)&g_dB[base + 64 + k2] = hi2;
        }
    }
}

// ---------------- CSR build: deterministic two-level scan --------------------
__global__ void __launch_bounds__(128) bsum_kernel(){
    const int t = threadIdx.x;
    const int node = blockIdx.x * 128 + t;
    int deg = (node < N_NODES) ? g_deg[node] : 0;
    #pragma unroll
    for (int s = 16; s > 0; s >>= 1) deg += __shfl_down_sync(0xffffffffu, deg, s);
    __shared__ int ws[4];
    if ((t & 31) == 0) ws[t >> 5] = deg;
    __syncthreads();
    if (t == 0) g_bsum[blockIdx.x] = ws[0] + ws[1] + ws[2] + ws[3];
}
__global__ void __launch_bounds__(256) bscan_kernel(){
    __shared__ int sm[256];
    const int t = threadIdx.x;
    int v = (t < NBLK) ? g_bsum[t] : 0;
    sm[t] = v; __syncthreads();
    for (int s = 1; s < 256; s <<= 1) {
        int u = (t >= s) ? sm[t - s] : 0;
        __syncthreads();
        sm[t] += u;
        __syncthreads();
    }
    if (t < NBLK) g_bpre[t] = sm[t] - v;   // exclusive prefix
}
__global__ void __launch_bounds__(128) offset_kernel(){
    const int t    = threadIdx.x;
    const int lane = t & 31;
    const int w    = t >> 5;
    const int node = blockIdx.x * 128 + t;
    const int deg  = (node < N_NODES) ? g_deg[node] : 0;

    int incl = deg;
    #pragma unroll
    for (int s = 1; s < 32; s <<= 1) {
        int v = __shfl_up_sync(0xffffffffu, incl, s);
        if (lane >= s) incl += v;
    }
    __shared__ int wsum[4];
    if (lane == 31) wsum[w] = incl;
    __syncthreads();
    if (t == 0) {
        int a = wsum[0], b = wsum[1], c = wsum[2];
        wsum[3] = a + b + c; wsum[2] = a + b; wsum[1] = a; wsum[0] = 0;
    }
    __syncthreads();
    const int off = g_bpre[blockIdx.x] + wsum[w] + incl - deg;
    if (node < N_NODES) { g_off[node] = off; g_cur[node] = off; }
}
__global__ void scatter_kernel(const int* __restrict__ ei){
    int e = blockIdx.x*blockDim.x+threadIdx.x;
    if (e<N_EDGES){
        int d = ei[N_EDGES+e];
        int p = atomicAdd(&g_cur[d],1);
        g_srcs[p] = ei[e];
    }
}

// ---------------- softmax + aggregate: warp per node ------------------------
__global__ void __launch_bounds__(256) agg_kernel(const float* __restrict__ bias_gat)
{
    const int wid  = threadIdx.x >> 5;
    const int lane = threadIdx.x & 31;
    const int node = blockIdx.x * 8 + wid;
    if (node >= N_NODES) return;

    const int off = g_off[node];
    const int deg = g_deg[node];

    float adv = 0.f, den = 0.f, pv = 0.f;
    if (lane < NH) {
        adv = g_ad[node * NH + lane];
        float l = g_as[node * NH + lane] + adv;
        l = (l > 0.f) ? l : NEG * l;
        pv = expf(l);
        den = pv;
    }

    const float* hrow = g_h + (size_t)node * HF;
    float acc[NH];
    #pragma unroll
    for (int h = 0; h < NH; h++)
        acc[h] = hrow[h * FH + lane] * __shfl_sync(0xffffffffu, pv, h);

    for (int e = 0; e < deg; e++) {
        const int s = g_srcs[off + e];
        float pe = 0.f;
        if (lane < NH) {
            float l = g_as[s * NH + lane] + adv;
            l = (l > 0.f) ? l : NEG * l;
            pe = expf(l);
            den += pe;
        }
        const float* srow = g_h + (size_t)s * HF;
        #pragma unroll
        for (int h = 0; h < NH; h++)
            acc[h] += srow[h * FH + lane] * __shfl_sync(0xffffffffu, pe, h);
    }

    #pragma unroll
    for (int h = 0; h < NH; h++) {
        const float d = __shfl_sync(0xffffffffu, den, h);
        const float v = acc[h] / d + bias_gat[h * FH + lane];
        g_gat[(size_t)node * HF + h * FH + lane] = fmaxf(v, 0.f);
    }
}

// ---------------- launch -----------------------------------------------------
extern "C" void kernel_launch(void* const* d_in, const int* in_sizes, int n_in,
                              void* d_out, int out_size)
{
    const float* x        = (const float*)d_in[0];
    const int*   ei       = (const int*)  d_in[1];
    const float* W        = (const float*)d_in[3];
    const float* att_src  = (const float*)d_in[4];
    const float* att_dst  = (const float*)d_in[5];
    const float* bias_gat = (const float*)d_in[6];
    const float* emb_W    = (const float*)d_in[7];
    const float* emb_b    = (const float*)d_in[8];
    const float* dec_W1   = (const float*)d_in[9];
    const float* dec_b1   = (const float*)d_in[10];
    const float* dec_W2   = (const float*)d_in[11];
    const float* dec_b2   = (const float*)d_in[12];

    float* recon = (float*)d_out;                              // [N, DIN]
    float* z     = (float*)d_out + (size_t)N_NODES*DIN;        // [N, DEMB]

    cudaFuncSetAttribute(gemm1_mma_kernel,
                         cudaFuncAttributeMaxDynamicSharedMemorySize, GSMT);
    cudaFuncSetAttribute(recon_mma_kernel,
                         cudaFuncAttributeMaxDynamicSharedMemorySize, RSMT);

    const int MB = (N_NODES + 127)/128;   // 235
    const int MB64 = N_PAD/64;            // 470

    // 0) operand prep (split zeroes g_deg; build_wB counts + packs W,W2)
    split_x_kernel<<<(int)(((size_t)N_PAD*KSEC/8 + 255)/256), 256>>>(x);
    build_wB_kernel<<<(HF*KTOT + 255)/256, 256>>>(W, dec_W2, ei);
    // 1) h = x @ W via mma.sync bf16x3 (+ fused a_s/a_d); BM=64 BK=64, 3 CTAs/SM
    gemm1_mma_kernel<<<dim3(2, MB64), 256, GSMT>>>(att_src, att_dst);
    // 2) CSR finish: deterministic two-level scan + scatter
    bsum_kernel   <<<MB, 128>>>();
    bscan_kernel  <<<1, 256>>>();
    offset_kernel <<<MB, 128>>>();
    scatter_kernel<<<(N_EDGES+255)/256,256>>>(ei);
    // 3) attention softmax + aggregate + bias + relu (warp per node)
    agg_kernel<<<(N_NODES+7)/8, 256>>>(bias_gat);
    // 4+5) fused z and d (d emitted as bf16x3)
    zd_kernel<<<MB, 256>>>(emb_W, emb_b, dec_W1, dec_b1, z);
    // 6) recon = d @ dec_W2 + dec_b2 via mma.sync bf16x3
    recon_mma_kernel<<<dim3(8, MB), 256, RSMT>>>(dec_b2, recon);
}